// round 1
// baseline (speedup 1.0000x reference)
#include <cuda_runtime.h>

#define NPTS  16384      // B*N
#define NB    4096       // points per batch
#define KNN   16
#define PTS   4          // points per group in main kernel
#define NGRP  (NPTS/PTS)

// smem float offsets for main kernel
#define O_WB   0
#define O_W1A  4096
#define O_W2A  8192
#define O_W2B  12288
#define O_W3A  16384
#define O_W3B  20480
#define O_W3C  24576
#define O_F    28672     // knn feats, reused for h4
#define O_H1   32768
#define O_H2   36864
#define O_H3   40960
#define O_C    45056     // per-point constants, PTS*256
#define SMEM_FLOATS 46080

__device__ __align__(16) int   g_knn[NPTS * KNN];
__device__ __align__(16) float g_const[NPTS * 256];

// ---------- packed f32x2 helpers ----------
static __device__ __forceinline__ unsigned long long pack2(float a, float b) {
    unsigned long long r;
    asm("mov.b64 %0, {%1, %2};" : "=l"(r) : "f"(a), "f"(b));
    return r;
}
static __device__ __forceinline__ void unpack2(unsigned long long v, float &a, float &b) {
    asm("mov.b64 {%0, %1}, %2;" : "=f"(a), "=f"(b) : "l"(v));
}
static __device__ __forceinline__ void ffma2(unsigned long long &d, unsigned long long a, unsigned long long b) {
    asm("fma.rn.f32x2 %0, %1, %2, %0;" : "+l"(d) : "l"(a), "l"(b));
}

// ================= KNN kernel =================
// thread-per-query; maintain top-17 (ascending d2), drop min (self).
__global__ void knn_kernel(const float* __restrict__ pos) {
    __shared__ float sx[512], sy[512], sz[512], ssq[512];
    int q = blockIdx.x * 256 + threadIdx.x;
    int b = q >> 12;
    float qx = pos[q * 3 + 0], qy = pos[q * 3 + 1], qz = pos[q * 3 + 2];
    float qs = qx * qx + qy * qy + qz * qz;

    float bd[17];
    int   bi[17];
#pragma unroll
    for (int i = 0; i < 17; i++) { bd[i] = 3.4e38f; bi[i] = 0; }

    int base = b << 12;
    for (int tile = 0; tile < NB; tile += 512) {
        __syncthreads();
        for (int i = threadIdx.x; i < 512; i += 256) {
            const float* p = pos + (size_t)(base + tile + i) * 3;
            float px = p[0], py = p[1], pz = p[2];
            sx[i] = px; sy[i] = py; sz[i] = pz;
            ssq[i] = px * px + py * py + pz * pz;
        }
        __syncthreads();
#pragma unroll 4
        for (int c = 0; c < 512; c++) {
            float d2 = qs + ssq[c] - 2.0f * (qx * sx[c] + qy * sy[c] + qz * sz[c]);
            if (d2 < bd[16]) {
                bd[16] = d2; bi[16] = tile + c;
#pragma unroll
                for (int i = 16; i > 0; --i) {
                    if (bd[i] < bd[i - 1]) {
                        float td = bd[i]; bd[i] = bd[i - 1]; bd[i - 1] = td;
                        int   ti = bi[i]; bi[i] = bi[i - 1]; bi[i - 1] = ti;
                    }
                }
            }
        }
    }
#pragma unroll
    for (int i = 0; i < 16; i++) g_knn[q * KNN + i] = bi[i + 1];
}

// ================= per-point constants kernel =================
// c[pt][0:64]=c1, [64:128]=c2, [128:192]=c3, [192:256]=c4
__global__ void const_kernel(const float* __restrict__ x,
                             const float* __restrict__ Wf,  const float* __restrict__ bf,
                             const float* __restrict__ Wm1, const float* __restrict__ bm1,
                             const float* __restrict__ Wm2, const float* __restrict__ bm2,
                             const float* __restrict__ Wl,  const float* __restrict__ bl) {
    extern __shared__ float sm[];
    float* Wc   = sm;               // 64*256
    float* bias = sm + 64 * 256;    // 256
    float* xs   = bias + 256;       // 64
    int t = threadIdx.x;
    for (int i = t; i < 64 * 256; i += 256) {
        int d = i >> 8, j = i & 255;
        float v;
        if (j < 64)       v = Wf[d * 64 + j] - Wf[(128 + d) * 64 + j];
        else if (j < 128) v = Wm1[(64 + d) * 64 + (j - 64)];
        else if (j < 192) v = Wm2[(128 + d) * 64 + (j - 128)];
        else              v = Wl[(192 + d) * 64 + (j - 192)];
        Wc[i] = v;
    }
    bias[t] = (t < 64) ? bf[t] : (t < 128) ? bm1[t - 64] : (t < 192) ? bm2[t - 128] : bl[t - 192];

    for (int pt = blockIdx.x; pt < NPTS; pt += gridDim.x) {
        __syncthreads();
        if (t < 64) xs[t] = x[(size_t)pt * 64 + t];
        __syncthreads();
        float acc = bias[t];
#pragma unroll 8
        for (int d = 0; d < 64; d++) acc = fmaf(xs[d], Wc[d * 256 + t], acc);
        g_const[(size_t)pt * 256 + t] = acc;
    }
}

// ================= main fused edge-MLP + max kernel =================
__global__ void __launch_bounds__(256, 1)
edge_mlp_kernel(const float* __restrict__ x,
                const float* __restrict__ Wf, const float* __restrict__ Wm1,
                const float* __restrict__ Wm2, const float* __restrict__ Wl,
                float* __restrict__ out) {
    extern __shared__ float sm[];
    int t = threadIdx.x;

    // Load variable weight slices once per block (7 x 64x64)
    for (int i = t; i < 4096; i += 256) {
        int d = i >> 6, j = i & 63;
        sm[O_WB  + i] = Wf[(64 + d) * 64 + j] + Wf[(128 + d) * 64 + j];
        sm[O_W1A + i] = Wm1[i];               // rows 0:64 of W_mid1
        sm[O_W2A + i] = Wm2[i];               // rows 0:64 of W_mid2 (x h2)
        sm[O_W2B + i] = Wm2[4096 + i];        // rows 64:128 (x h1)
        sm[O_W3A + i] = Wl[i];                // rows 0:64 of W_last (x h3)
        sm[O_W3B + i] = Wl[4096 + i];         // rows 64:128 (x h2)
        sm[O_W3C + i] = Wl[8192 + i];         // rows 128:192 (x h1)
    }
    __syncthreads();

    const int k  = t >> 4;      // neighbor index 0..15
    const int jb = (t & 15) << 2; // output column base

    for (int grp = blockIdx.x; grp < NGRP; grp += gridDim.x) {
        int base = grp * PTS;       // global point index
        int b = base >> 12;

        // ---- gather: knn feats + constants ----
        {
            int r  = t >> 2;        // row 0..63 -> (p = r>>4, k = r&15)
            int q4 = t & 3;
            int nb = g_knn[grp * 64 + r];
            const float4* src = (const float4*)(x + ((size_t)(b << 12) + nb) * 64) + (q4 << 2);
            float4* dst = (float4*)(sm + O_F + (r << 6)) + (q4 << 2);
#pragma unroll
            for (int u = 0; u < 4; u++) dst[u] = src[u];
            ((float4*)(sm + O_C))[t] = ((const float4*)(g_const + (size_t)grp * 1024))[t];
        }
        __syncthreads();

        unsigned long long a0[PTS], a1[PTS];

        // accumulate: acc[p] += Hin[p][k][:] @ W[:, jb..jb+3]
        auto accum = [&](int hoff, int woff) {
#pragma unroll 4
            for (int d = 0; d < 64; d++) {
                float4 w = *(const float4*)(sm + woff + (d << 6) + jb);
                unsigned long long w01 = pack2(w.x, w.y);
                unsigned long long w23 = pack2(w.z, w.w);
#pragma unroll
                for (int p = 0; p < PTS; p++) {
                    float hv = sm[hoff + (((p << 4) + k) << 6) + d];
                    unsigned long long h2v = pack2(hv, hv);
                    ffma2(a0[p], h2v, w01);
                    ffma2(a1[p], h2v, w23);
                }
            }
        };
        auto init_acc = [&](int coff) {
#pragma unroll
            for (int p = 0; p < PTS; p++) {
                const float* c = sm + O_C + (p << 8) + coff + jb;
                a0[p] = pack2(c[0], c[1]);
                a1[p] = pack2(c[2], c[3]);
            }
        };
        auto store_h = [&](int hoff, bool relu) {
#pragma unroll
            for (int p = 0; p < PTS; p++) {
                float v0, v1, v2, v3;
                unpack2(a0[p], v0, v1);
                unpack2(a1[p], v2, v3);
                if (relu) {
                    v0 = fmaxf(v0, 0.0f); v1 = fmaxf(v1, 0.0f);
                    v2 = fmaxf(v2, 0.0f); v3 = fmaxf(v3, 0.0f);
                }
                *(float4*)(sm + hoff + (((p << 4) + k) << 6) + jb) = make_float4(v0, v1, v2, v3);
            }
        };

        // layer 1: h1 = relu(c1 + knn @ WB)
        init_acc(0);   accum(O_F, O_WB);                          store_h(O_H1, true);
        __syncwarp();
        // layer 2: h2 = relu(c2 + h1 @ W1A)
        init_acc(64);  accum(O_H1, O_W1A);                        store_h(O_H2, true);
        __syncwarp();
        // layer 3: h3 = relu(c3 + h2 @ W2A + h1 @ W2B)
        init_acc(128); accum(O_H2, O_W2A); accum(O_H1, O_W2B);    store_h(O_H3, true);
        __syncwarp();
        // layer 4: h4 = c4 + h3 @ W3A + h2 @ W3B + h1 @ W3C   (no relu), store into F region
        init_acc(192); accum(O_H3, O_W3A); accum(O_H2, O_W3B); accum(O_H1, O_W3C);
        store_h(O_F, false);
        __syncthreads();

        // ---- max over K and write output [h4|h3|h2|h1|x] ----
        {
            int p = t >> 6, j = t & 63;
            int pt = base + p;
            size_t orow = (size_t)pt * 320;
            float m4 = -3.4e38f, m3 = -3.4e38f, m2 = -3.4e38f, m1 = -3.4e38f;
#pragma unroll
            for (int kk = 0; kk < 16; kk++) {
                int off = (((p << 4) + kk) << 6) + j;
                m4 = fmaxf(m4, sm[O_F  + off]);
                m3 = fmaxf(m3, sm[O_H3 + off]);
                m2 = fmaxf(m2, sm[O_H2 + off]);
                m1 = fmaxf(m1, sm[O_H1 + off]);
            }
            out[orow +   0 + j] = m4;
            out[orow +  64 + j] = m3;
            out[orow + 128 + j] = m2;
            out[orow + 192 + j] = m1;
            out[orow + 256 + j] = x[(size_t)pt * 64 + j];
        }
        __syncthreads();
    }
}

extern "C" void kernel_launch(void* const* d_in, const int* in_sizes, int n_in,
                              void* d_out, int out_size) {
    const float* x   = (const float*)d_in[0];
    const float* pos = (const float*)d_in[1];
    const float* Wf  = (const float*)d_in[2];
    const float* bf  = (const float*)d_in[3];
    const float* Wm1 = (const float*)d_in[4];
    const float* bm1 = (const float*)d_in[5];
    const float* Wm2 = (const float*)d_in[6];
    const float* bm2 = (const float*)d_in[7];
    const float* Wl  = (const float*)d_in[8];
    const float* bl  = (const float*)d_in[9];
    float* out = (float*)d_out;

    cudaFuncSetAttribute(const_kernel, cudaFuncAttributeMaxDynamicSharedMemorySize,
                         (64 * 256 + 256 + 64) * 4);
    cudaFuncSetAttribute(edge_mlp_kernel, cudaFuncAttributeMaxDynamicSharedMemorySize,
                         SMEM_FLOATS * 4);

    knn_kernel<<<64, 256>>>(pos);
    const_kernel<<<128, 256, (64 * 256 + 256 + 64) * 4>>>(x, Wf, bf, Wm1, bm1, Wm2, bm2, Wl, bl);
    edge_mlp_kernel<<<148, 256, SMEM_FLOATS * 4>>>(x, Wf, Wm1, Wm2, Wl, out);
}

// round 2
// speedup vs baseline: 1.1511x; 1.1511x over previous
#include <cuda_runtime.h>

#define NPTS  16384
#define KNN_K 16
#define QB    64

// ---- smem float offsets for edge_mlp ----
#define O_WB   0
#define O_W1A  4096
#define O_W2A  8192
#define O_W2B  12288
#define O_W3A  16384
#define O_W3B  20480
#define O_W3C  24576
#define O_F    28672
#define O_H1   32768
#define O_H2   36864
#define O_H3   40960
#define O_H4   45056
#define O_C    49152
#define SMEM_FLOATS 50176

__device__ __align__(16) int   g_knn[NPTS * KNN_K];
__device__ __align__(16) float g_const[NPTS * 256];

// ---------- packed f32x2 helpers ----------
static __device__ __forceinline__ unsigned long long pack2(float a, float b) {
    unsigned long long r;
    asm("mov.b64 %0, {%1, %2};" : "=l"(r) : "f"(a), "f"(b));
    return r;
}
static __device__ __forceinline__ void unpack2(unsigned long long v, float &a, float &b) {
    asm("mov.b64 {%0, %1}, %2;" : "=f"(a), "=f"(b) : "l"(v));
}
static __device__ __forceinline__ void ffma2(unsigned long long &d, unsigned long long a, unsigned long long b) {
    asm("fma.rn.f32x2 %0, %1, %2, %0;" : "+l"(d) : "l"(a), "l"(b));
}

// ================= KNN: radix-select =================
// find smallest digit B with cum >= target; cb = count strictly below bin B.
static __device__ __forceinline__ void warp_scan_find(const unsigned* __restrict__ h, unsigned target,
                                                      unsigned* outB, unsigned* outCb) {
    int lane = threadIdx.x & 31;
    unsigned loc[8], s = 0;
#pragma unroll
    for (int j = 0; j < 8; j++) { loc[j] = h[lane * 8 + j]; s += loc[j]; }
    unsigned pre = s;
#pragma unroll
    for (int o = 1; o < 32; o <<= 1) {
        unsigned v = __shfl_up_sync(0xffffffffu, pre, o);
        if (lane >= o) pre += v;
    }
    unsigned excl = pre - s;
    bool mine = (excl < target) && (excl + s >= target);
    unsigned mb = __ballot_sync(0xffffffffu, mine);
    int lead = __ffs(mb) - 1;
    if (lane == lead) {
        unsigned run = excl, B = 0, cbv = 0;
        bool done = false;
#pragma unroll
        for (int j = 0; j < 8; j++) {
            if (!done && run + loc[j] >= target) { B = lane * 8 + j; cbv = run; done = true; }
            run += loc[j];
        }
        *outB = B; *outCb = cbv;
    }
}

__global__ void __launch_bounds__(256, 2) knn_kernel(const float* __restrict__ pos) {
    extern __shared__ char smraw[];
    float4*   tile  = (float4*)smraw;                    // 4096*16 = 65536
    unsigned* keys  = (unsigned*)(smraw + 65536);        // 16384
    unsigned* hist  = (unsigned*)(smraw + 81920);        // 1024
    unsigned* hist2 = (unsigned*)(smraw + 82944);        // 1024
    unsigned* bufK  = (unsigned*)(smraw + 83968);        // 512
    int*      bufI  = (int*)(smraw + 84480);             // 512
    unsigned* sv    = (unsigned*)(smraw + 84992);        // 16

    int t = threadIdx.x;
    int lane = t & 31;
    int b = blockIdx.x >> 6;
    int qoff = (blockIdx.x & 63) * QB;
    const float* P = pos + ((size_t)(b << 12)) * 3;
    for (int i = t; i < 4096; i += 256) {
        float px = P[3 * i], py = P[3 * i + 1], pz = P[3 * i + 2];
        tile[i] = make_float4(px, py, pz, px * px + py * py + pz * pz);
    }
    __syncthreads();

    for (int qi = 0; qi < QB; qi++) {
        int ql = qoff + qi;
        float4 qp = tile[ql];
        float qx = qp.x, qy = qp.y, qz = qp.z, qs = qp.w;
        hist[t] = 0; hist2[t] = 0;
        if (t == 0) sv[3] = 0;
        __syncthreads();

        // keys + level-1 histogram (match-aggregated atomics)
#pragma unroll 4
        for (int i = 0; i < 16; i++) {
            int c = t + (i << 8);
            float4 pc = tile[c];
            float d2 = qs + pc.w - 2.0f * (qx * pc.x + qy * pc.y + qz * pc.z);
            unsigned kb = __float_as_uint(d2);
            kb ^= ((unsigned)((int)kb >> 31)) | 0x80000000u;
            keys[c] = kb;
            unsigned bin = kb >> 24;
            unsigned m = __match_any_sync(0xffffffffu, bin);
            if (lane == __ffs(m) - 1) atomicAdd(&hist[bin], (unsigned)__popc(m));
        }
        __syncthreads();
        if (t < 32) warp_scan_find(hist, 17u, sv + 0, sv + 1);
        __syncthreads();
        unsigned B = sv[0], cb = sv[1];

        // level-2 histogram within bin B
#pragma unroll 4
        for (int i = 0; i < 16; i++) {
            int c = t + (i << 8);
            unsigned key = keys[c];
            unsigned b2 = ((key >> 24) == B) ? ((key >> 16) & 255u) : 0xffffffffu;
            unsigned m = __match_any_sync(0xffffffffu, b2);
            if (b2 != 0xffffffffu && lane == __ffs(m) - 1) atomicAdd(&hist2[b2], (unsigned)__popc(m));
        }
        __syncthreads();
        if (t < 32) warp_scan_find(hist2, 17u - cb, sv + 2, sv + 1);
        __syncthreads();
        unsigned cut = (B << 8) | sv[2];

        // collect survivors
#pragma unroll 4
        for (int i = 0; i < 16; i++) {
            int c = t + (i << 8);
            unsigned key = keys[c];
            if ((key >> 16) <= cut) {
                unsigned p = atomicAdd(&sv[3], 1u);
                if (p < 128u) { bufK[p] = key; bufI[p] = c; }
            }
        }
        __syncthreads();

        // exact rank by (key, idx) lexicographic count; rank 0 = self dropped
        int M = min(sv[3], 128u);
        if (t < M) {
            unsigned mk = bufK[t]; int mi = bufI[t];
            int r = 0;
            for (int j = 0; j < M; j++) {
                unsigned ok = bufK[j]; int oi = bufI[j];
                if (ok < mk || (ok == mk && oi < mi)) r++;
            }
            if (r >= 1 && r <= 16) {
                int qg = (b << 12) + ql;
                g_knn[qg * KNN_K + (r - 1)] = mi;
            }
        }
        __syncthreads();
    }
}

// ================= per-point constants =================
__global__ void const_kernel(const float* __restrict__ x,
                             const float* __restrict__ Wf,  const float* __restrict__ bf,
                             const float* __restrict__ Wm1, const float* __restrict__ bm1,
                             const float* __restrict__ Wm2, const float* __restrict__ bm2,
                             const float* __restrict__ Wl,  const float* __restrict__ bl) {
    extern __shared__ float sm[];
    float* Wc   = sm;               // 64*256
    float* bias = sm + 64 * 256;    // 256
    float* xs   = bias + 256;       // 64
    int t = threadIdx.x;
    for (int i = t; i < 64 * 256; i += 256) {
        int d = i >> 8, j = i & 255;
        float v;
        if (j < 64)       v = Wf[d * 64 + j] - Wf[(128 + d) * 64 + j];
        else if (j < 128) v = Wm1[(64 + d) * 64 + (j - 64)];
        else if (j < 192) v = Wm2[(128 + d) * 64 + (j - 128)];
        else              v = Wl[(192 + d) * 64 + (j - 192)];
        Wc[i] = v;
    }
    bias[t] = (t < 64) ? bf[t] : (t < 128) ? bm1[t - 64] : (t < 192) ? bm2[t - 128] : bl[t - 192];

    for (int pt = blockIdx.x; pt < NPTS; pt += gridDim.x) {
        __syncthreads();
        if (t < 64) xs[t] = x[(size_t)pt * 64 + t];
        __syncthreads();
        float acc = bias[t];
#pragma unroll 8
        for (int d = 0; d < 64; d++) acc = fmaf(xs[d], Wc[d * 256 + t], acc);
        g_const[(size_t)pt * 256 + t] = acc;
    }
}

// ================= fused edge-MLP + max =================
__global__ void __launch_bounds__(256, 1)
edge_mlp_kernel(const float* __restrict__ x,
                const float* __restrict__ Wf, const float* __restrict__ Wm1,
                const float* __restrict__ Wm2, const float* __restrict__ Wl,
                float* __restrict__ out) {
    extern __shared__ float sm[];
    int t = threadIdx.x;

    for (int i = t; i < 4096; i += 256) {
        int d = i >> 6, j = i & 63;
        sm[O_WB  + i] = Wf[(64 + d) * 64 + j] + Wf[(128 + d) * 64 + j];
        sm[O_W1A + i] = Wm1[i];
        sm[O_W2A + i] = Wm2[i];
        sm[O_W2B + i] = Wm2[4096 + i];
        sm[O_W3A + i] = Wl[i];
        sm[O_W3B + i] = Wl[4096 + i];
        sm[O_W3C + i] = Wl[8192 + i];
    }
    __syncthreads();

    const int k  = t >> 4;
    const int jb = (t & 15) << 2;
    unsigned long long a[4][2];

    for (int grp = blockIdx.x; grp < NPTS / 4; grp += gridDim.x) {
        int base = grp * 4;
        int b = base >> 12;

        // gather knn feats ([p][k][d] contiguous rows) + constants
        {
            int r  = t >> 2;
            int q4 = t & 3;
            int nb = g_knn[grp * 64 + r];
            const float4* src = (const float4*)(x + ((size_t)(b << 12) + nb) * 64) + (q4 << 2);
            float4* dst = (float4*)(sm + O_F + (r << 6)) + (q4 << 2);
#pragma unroll
            for (int u = 0; u < 4; u++) dst[u] = src[u];
            ((float4*)(sm + O_C))[t] = ((const float4*)(g_const + (size_t)grp * 1024))[t];
        }
        __syncthreads();

        auto init_acc = [&](int coff) {
#pragma unroll
            for (int j = 0; j < 4; j++) {
                a[j][0] = pack2(sm[O_C +       coff + jb + j], sm[O_C + 256 + coff + jb + j]);
                a[j][1] = pack2(sm[O_C + 512 + coff + jb + j], sm[O_C + 768 + coff + jb + j]);
            }
        };
        // h stored [k][d][p]: one LDS.128 = both p-pairs, ready for f32x2
        auto accum = [&](int hoff, int woff) {
#pragma unroll 8
            for (int d = 0; d < 64; d++) {
                float4 w = *(const float4*)(sm + woff + (d << 6) + jb);
                ulonglong2 h2 = *(const ulonglong2*)(sm + hoff + (k << 8) + (d << 2));
                unsigned long long w0 = pack2(w.x, w.x), w1 = pack2(w.y, w.y);
                unsigned long long w2 = pack2(w.z, w.z), w3 = pack2(w.w, w.w);
                ffma2(a[0][0], h2.x, w0); ffma2(a[0][1], h2.y, w0);
                ffma2(a[1][0], h2.x, w1); ffma2(a[1][1], h2.y, w1);
                ffma2(a[2][0], h2.x, w2); ffma2(a[2][1], h2.y, w2);
                ffma2(a[3][0], h2.x, w3); ffma2(a[3][1], h2.y, w3);
            }
        };
        // layer-1 input is [p][k][d]
        auto accum_f = [&](int woff) {
#pragma unroll 8
            for (int d = 0; d < 64; d++) {
                float4 w = *(const float4*)(sm + woff + (d << 6) + jb);
                float f0 = sm[O_F +        (k << 6) + d];
                float f1 = sm[O_F + 1024 + (k << 6) + d];
                float f2 = sm[O_F + 2048 + (k << 6) + d];
                float f3 = sm[O_F + 3072 + (k << 6) + d];
                unsigned long long hA = pack2(f0, f1), hB = pack2(f2, f3);
                unsigned long long w0 = pack2(w.x, w.x), w1 = pack2(w.y, w.y);
                unsigned long long w2 = pack2(w.z, w.z), w3 = pack2(w.w, w.w);
                ffma2(a[0][0], hA, w0); ffma2(a[0][1], hB, w0);
                ffma2(a[1][0], hA, w1); ffma2(a[1][1], hB, w1);
                ffma2(a[2][0], hA, w2); ffma2(a[2][1], hB, w2);
                ffma2(a[3][0], hA, w3); ffma2(a[3][1], hB, w3);
            }
        };
        auto store_h = [&](int hoff, bool relu) {
#pragma unroll
            for (int j = 0; j < 4; j++) {
                float v0, v1, v2, v3;
                unpack2(a[j][0], v0, v1); unpack2(a[j][1], v2, v3);
                if (relu) {
                    v0 = fmaxf(v0, 0.0f); v1 = fmaxf(v1, 0.0f);
                    v2 = fmaxf(v2, 0.0f); v3 = fmaxf(v3, 0.0f);
                }
                *(float4*)(sm + hoff + (k << 8) + ((jb + j) << 2)) = make_float4(v0, v1, v2, v3);
            }
        };

        init_acc(0);   accum_f(O_WB);                              store_h(O_H1, true);
        __syncwarp();
        init_acc(64);  accum(O_H1, O_W1A);                         store_h(O_H2, true);
        __syncwarp();
        init_acc(128); accum(O_H2, O_W2A); accum(O_H1, O_W2B);     store_h(O_H3, true);
        __syncwarp();
        init_acc(192); accum(O_H3, O_W3A); accum(O_H2, O_W3B); accum(O_H1, O_W3C);
        store_h(O_H4, false);
        __syncthreads();

        // max over K, conflict-free mapping (p = t&3)
        {
            int p = t & 3, j = t >> 2;
            int pt = base + p;
            size_t orow = (size_t)pt * 320;
            float m4 = -3.4e38f, m3 = -3.4e38f, m2 = -3.4e38f, m1 = -3.4e38f;
#pragma unroll
            for (int kk = 0; kk < 16; kk++) {
                int off = (kk << 8) + (j << 2) + p;
                m1 = fmaxf(m1, sm[O_H1 + off]);
                m2 = fmaxf(m2, sm[O_H2 + off]);
                m3 = fmaxf(m3, sm[O_H3 + off]);
                m4 = fmaxf(m4, sm[O_H4 + off]);
            }
            out[orow +       j] = m4;
            out[orow +  64 + j] = m3;
            out[orow + 128 + j] = m2;
            out[orow + 192 + j] = m1;
            out[orow + 256 + j] = x[(size_t)pt * 64 + j];
        }
        __syncthreads();
    }
}

extern "C" void kernel_launch(void* const* d_in, const int* in_sizes, int n_in,
                              void* d_out, int out_size) {
    const float* x   = (const float*)d_in[0];
    const float* pos = (const float*)d_in[1];
    const float* Wf  = (const float*)d_in[2];
    const float* bf  = (const float*)d_in[3];
    const float* Wm1 = (const float*)d_in[4];
    const float* bm1 = (const float*)d_in[5];
    const float* Wm2 = (const float*)d_in[6];
    const float* bm2 = (const float*)d_in[7];
    const float* Wl  = (const float*)d_in[8];
    const float* bl  = (const float*)d_in[9];
    float* out = (float*)d_out;

    cudaFuncSetAttribute(knn_kernel, cudaFuncAttributeMaxDynamicSharedMemorySize, 85248);
    cudaFuncSetAttribute(const_kernel, cudaFuncAttributeMaxDynamicSharedMemorySize,
                         (64 * 256 + 256 + 64) * 4);
    cudaFuncSetAttribute(edge_mlp_kernel, cudaFuncAttributeMaxDynamicSharedMemorySize,
                         SMEM_FLOATS * 4);

    knn_kernel<<<256, 256, 85248>>>(pos);
    const_kernel<<<256, 256, (64 * 256 + 256 + 64) * 4>>>(x, Wf, bf, Wm1, bm1, Wm2, bm2, Wl, bl);
    edge_mlp_kernel<<<148, 256, SMEM_FLOATS * 4>>>(x, Wf, Wm1, Wm2, Wl, out);
}

// round 3
// speedup vs baseline: 1.1516x; 1.0004x over previous
#include <cuda_runtime.h>

#define NPTS  16384
#define KNN_K 16
#define QB    64

// ---- smem float offsets for edge_mlp ----
#define O_WB   0
#define O_W1A  4096
#define O_W2A  8192
#define O_W2B  12288
#define O_W3A  16384
#define O_W3B  20480
#define O_W3C  24576
#define O_F    28672
#define O_H1   32768
#define O_H2   36864
#define O_H3   40960
#define O_H4   45056
#define O_C    49152
#define SMEM_FLOATS 50176

__device__ __align__(16) int   g_knn[NPTS * KNN_K];
__device__ __align__(16) float g_const[NPTS * 256];

// ---------- packed f32x2 helpers ----------
static __device__ __forceinline__ unsigned long long pack2(float a, float b) {
    unsigned long long r;
    asm("mov.b64 %0, {%1, %2};" : "=l"(r) : "f"(a), "f"(b));
    return r;
}
static __device__ __forceinline__ void unpack2(unsigned long long v, float &a, float &b) {
    asm("mov.b64 {%0, %1}, %2;" : "=f"(a), "=f"(b) : "l"(v));
}
static __device__ __forceinline__ void ffma2(unsigned long long &d, unsigned long long a, unsigned long long b) {
    asm("fma.rn.f32x2 %0, %1, %2, %0;" : "+l"(d) : "l"(a), "l"(b));
}

// ================= KNN: radix-select =================
// find smallest digit B with cum >= target; cb = count strictly below bin B.
static __device__ __forceinline__ void warp_scan_find(const unsigned* __restrict__ h, unsigned target,
                                                      unsigned* outB, unsigned* outCb) {
    int lane = threadIdx.x & 31;
    unsigned loc[8], s = 0;
#pragma unroll
    for (int j = 0; j < 8; j++) { loc[j] = h[lane * 8 + j]; s += loc[j]; }
    unsigned pre = s;
#pragma unroll
    for (int o = 1; o < 32; o <<= 1) {
        unsigned v = __shfl_up_sync(0xffffffffu, pre, o);
        if (lane >= o) pre += v;
    }
    unsigned excl = pre - s;
    bool mine = (excl < target) && (excl + s >= target);
    unsigned mb = __ballot_sync(0xffffffffu, mine);
    int lead = __ffs(mb) - 1;
    if (lane == lead) {
        unsigned run = excl, B = 0, cbv = 0;
        bool done = false;
#pragma unroll
        for (int j = 0; j < 8; j++) {
            if (!done && run + loc[j] >= target) { B = lane * 8 + j; cbv = run; done = true; }
            run += loc[j];
        }
        *outB = B; *outCb = cbv;
    }
}

__global__ void __launch_bounds__(256, 2) knn_kernel(const float* __restrict__ pos) {
    extern __shared__ char smraw[];
    float4*   tile  = (float4*)smraw;                    // 4096*16 = 65536
    unsigned* keys  = (unsigned*)(smraw + 65536);        // 16384
    unsigned* hist  = (unsigned*)(smraw + 81920);        // 1024
    unsigned* hist2 = (unsigned*)(smraw + 82944);        // 1024
    unsigned* bufK  = (unsigned*)(smraw + 83968);        // 512
    int*      bufI  = (int*)(smraw + 84480);             // 512
    unsigned* sv    = (unsigned*)(smraw + 84992);        // 16

    int t = threadIdx.x;
    int lane = t & 31;
    int b = blockIdx.x >> 6;
    int qoff = (blockIdx.x & 63) * QB;
    const float* P = pos + ((size_t)(b << 12)) * 3;
    for (int i = t; i < 4096; i += 256) {
        float px = P[3 * i], py = P[3 * i + 1], pz = P[3 * i + 2];
        tile[i] = make_float4(px, py, pz, px * px + py * py + pz * pz);
    }
    __syncthreads();

    for (int qi = 0; qi < QB; qi++) {
        int ql = qoff + qi;
        float4 qp = tile[ql];
        float qx = qp.x, qy = qp.y, qz = qp.z, qs = qp.w;
        hist[t] = 0; hist2[t] = 0;
        if (t == 0) sv[3] = 0;
        __syncthreads();

        // keys + level-1 histogram (match-aggregated atomics)
#pragma unroll 4
        for (int i = 0; i < 16; i++) {
            int c = t + (i << 8);
            float4 pc = tile[c];
            float d2 = qs + pc.w - 2.0f * (qx * pc.x + qy * pc.y + qz * pc.z);
            unsigned kb = __float_as_uint(d2);
            kb ^= ((unsigned)((int)kb >> 31)) | 0x80000000u;
            keys[c] = kb;
            unsigned bin = kb >> 24;
            unsigned m = __match_any_sync(0xffffffffu, bin);
            if (lane == __ffs(m) - 1) atomicAdd(&hist[bin], (unsigned)__popc(m));
        }
        __syncthreads();
        if (t < 32) warp_scan_find(hist, 17u, sv + 0, sv + 1);
        __syncthreads();
        unsigned B = sv[0], cb = sv[1];

        // level-2 histogram within bin B
#pragma unroll 4
        for (int i = 0; i < 16; i++) {
            int c = t + (i << 8);
            unsigned key = keys[c];
            unsigned b2 = ((key >> 24) == B) ? ((key >> 16) & 255u) : 0xffffffffu;
            unsigned m = __match_any_sync(0xffffffffu, b2);
            if (b2 != 0xffffffffu && lane == __ffs(m) - 1) atomicAdd(&hist2[b2], (unsigned)__popc(m));
        }
        __syncthreads();
        if (t < 32) warp_scan_find(hist2, 17u - cb, sv + 2, sv + 1);
        __syncthreads();
        unsigned cut = (B << 8) | sv[2];

        // collect survivors
#pragma unroll 4
        for (int i = 0; i < 16; i++) {
            int c = t + (i << 8);
            unsigned key = keys[c];
            if ((key >> 16) <= cut) {
                unsigned p = atomicAdd(&sv[3], 1u);
                if (p < 128u) { bufK[p] = key; bufI[p] = c; }
            }
        }
        __syncthreads();

        // exact rank by (key, idx) lexicographic count; rank 0 = self dropped
        int M = min(sv[3], 128u);
        if (t < M) {
            unsigned mk = bufK[t]; int mi = bufI[t];
            int r = 0;
            for (int j = 0; j < M; j++) {
                unsigned ok = bufK[j]; int oi = bufI[j];
                if (ok < mk || (ok == mk && oi < mi)) r++;
            }
            if (r >= 1 && r <= 16) {
                int qg = (b << 12) + ql;
                g_knn[qg * KNN_K + (r - 1)] = mi;
            }
        }
        __syncthreads();
    }
}

// ================= per-point constants =================
__global__ void const_kernel(const float* __restrict__ x,
                             const float* __restrict__ Wf,  const float* __restrict__ bf,
                             const float* __restrict__ Wm1, const float* __restrict__ bm1,
                             const float* __restrict__ Wm2, const float* __restrict__ bm2,
                             const float* __restrict__ Wl,  const float* __restrict__ bl) {
    extern __shared__ float sm[];
    float* Wc   = sm;               // 64*256
    float* bias = sm + 64 * 256;    // 256
    float* xs   = bias + 256;       // 64
    int t = threadIdx.x;
    for (int i = t; i < 64 * 256; i += 256) {
        int d = i >> 8, j = i & 255;
        float v;
        if (j < 64)       v = Wf[d * 64 + j] - Wf[(128 + d) * 64 + j];
        else if (j < 128) v = Wm1[(64 + d) * 64 + (j - 64)];
        else if (j < 192) v = Wm2[(128 + d) * 64 + (j - 128)];
        else              v = Wl[(192 + d) * 64 + (j - 192)];
        Wc[i] = v;
    }
    bias[t] = (t < 64) ? bf[t] : (t < 128) ? bm1[t - 64] : (t < 192) ? bm2[t - 128] : bl[t - 192];

    for (int pt = blockIdx.x; pt < NPTS; pt += gridDim.x) {
        __syncthreads();
        if (t < 64) xs[t] = x[(size_t)pt * 64 + t];
        __syncthreads();
        float acc = bias[t];
#pragma unroll 8
        for (int d = 0; d < 64; d++) acc = fmaf(xs[d], Wc[d * 256 + t], acc);
        g_const[(size_t)pt * 256 + t] = acc;
    }
}

// ================= fused edge-MLP + max =================
__global__ void __launch_bounds__(256, 1)
edge_mlp_kernel(const float* __restrict__ x,
                const float* __restrict__ Wf, const float* __restrict__ Wm1,
                const float* __restrict__ Wm2, const float* __restrict__ Wl,
                float* __restrict__ out) {
    extern __shared__ float sm[];
    int t = threadIdx.x;

    for (int i = t; i < 4096; i += 256) {
        int d = i >> 6, j = i & 63;
        sm[O_WB  + i] = Wf[(64 + d) * 64 + j] + Wf[(128 + d) * 64 + j];
        sm[O_W1A + i] = Wm1[i];
        sm[O_W2A + i] = Wm2[i];
        sm[O_W2B + i] = Wm2[4096 + i];
        sm[O_W3A + i] = Wl[i];
        sm[O_W3B + i] = Wl[4096 + i];
        sm[O_W3C + i] = Wl[8192 + i];
    }
    __syncthreads();

    const int k  = t >> 4;
    const int jb = (t & 15) << 2;
    unsigned long long a[4][2];

    for (int grp = blockIdx.x; grp < NPTS / 4; grp += gridDim.x) {
        int base = grp * 4;
        int b = base >> 12;

        // gather knn feats ([p][k][d] contiguous rows) + constants
        {
            int r  = t >> 2;
            int q4 = t & 3;
            int nb = g_knn[grp * 64 + r];
            const float4* src = (const float4*)(x + ((size_t)(b << 12) + nb) * 64) + (q4 << 2);
            float4* dst = (float4*)(sm + O_F + (r << 6)) + (q4 << 2);
#pragma unroll
            for (int u = 0; u < 4; u++) dst[u] = src[u];
            ((float4*)(sm + O_C))[t] = ((const float4*)(g_const + (size_t)grp * 1024))[t];
        }
        __syncthreads();

        auto init_acc = [&](int coff) {
#pragma unroll
            for (int j = 0; j < 4; j++) {
                a[j][0] = pack2(sm[O_C +       coff + jb + j], sm[O_C + 256 + coff + jb + j]);
                a[j][1] = pack2(sm[O_C + 512 + coff + jb + j], sm[O_C + 768 + coff + jb + j]);
            }
        };
        // h stored [k][d][p]: one LDS.128 = both p-pairs, ready for f32x2
        auto accum = [&](int hoff, int woff) {
#pragma unroll 8
            for (int d = 0; d < 64; d++) {
                float4 w = *(const float4*)(sm + woff + (d << 6) + jb);
                ulonglong2 h2 = *(const ulonglong2*)(sm + hoff + (k << 8) + (d << 2));
                unsigned long long w0 = pack2(w.x, w.x), w1 = pack2(w.y, w.y);
                unsigned long long w2 = pack2(w.z, w.z), w3 = pack2(w.w, w.w);
                ffma2(a[0][0], h2.x, w0); ffma2(a[0][1], h2.y, w0);
                ffma2(a[1][0], h2.x, w1); ffma2(a[1][1], h2.y, w1);
                ffma2(a[2][0], h2.x, w2); ffma2(a[2][1], h2.y, w2);
                ffma2(a[3][0], h2.x, w3); ffma2(a[3][1], h2.y, w3);
            }
        };
        // layer-1 input is [p][k][d]
        auto accum_f = [&](int woff) {
#pragma unroll 8
            for (int d = 0; d < 64; d++) {
                float4 w = *(const float4*)(sm + woff + (d << 6) + jb);
                float f0 = sm[O_F +        (k << 6) + d];
                float f1 = sm[O_F + 1024 + (k << 6) + d];
                float f2 = sm[O_F + 2048 + (k << 6) + d];
                float f3 = sm[O_F + 3072 + (k << 6) + d];
                unsigned long long hA = pack2(f0, f1), hB = pack2(f2, f3);
                unsigned long long w0 = pack2(w.x, w.x), w1 = pack2(w.y, w.y);
                unsigned long long w2 = pack2(w.z, w.z), w3 = pack2(w.w, w.w);
                ffma2(a[0][0], hA, w0); ffma2(a[0][1], hB, w0);
                ffma2(a[1][0], hA, w1); ffma2(a[1][1], hB, w1);
                ffma2(a[2][0], hA, w2); ffma2(a[2][1], hB, w2);
                ffma2(a[3][0], hA, w3); ffma2(a[3][1], hB, w3);
            }
        };
        auto store_h = [&](int hoff, bool relu) {
#pragma unroll
            for (int j = 0; j < 4; j++) {
                float v0, v1, v2, v3;
                unpack2(a[j][0], v0, v1); unpack2(a[j][1], v2, v3);
                if (relu) {
                    v0 = fmaxf(v0, 0.0f); v1 = fmaxf(v1, 0.0f);
                    v2 = fmaxf(v2, 0.0f); v3 = fmaxf(v3, 0.0f);
                }
                *(float4*)(sm + hoff + (k << 8) + ((jb + j) << 2)) = make_float4(v0, v1, v2, v3);
            }
        };

        init_acc(0);   accum_f(O_WB);                              store_h(O_H1, true);
        __syncwarp();
        init_acc(64);  accum(O_H1, O_W1A);                         store_h(O_H2, true);
        __syncwarp();
        init_acc(128); accum(O_H2, O_W2A); accum(O_H1, O_W2B);     store_h(O_H3, true);
        __syncwarp();
        init_acc(192); accum(O_H3, O_W3A); accum(O_H2, O_W3B); accum(O_H1, O_W3C);
        store_h(O_H4, false);
        __syncthreads();

        // max over K, conflict-free mapping (p = t&3)
        {
            int p = t & 3, j = t >> 2;
            int pt = base + p;
            size_t orow = (size_t)pt * 320;
            float m4 = -3.4e38f, m3 = -3.4e38f, m2 = -3.4e38f, m1 = -3.4e38f;
#pragma unroll
            for (int kk = 0; kk < 16; kk++) {
                int off = (kk << 8) + (j << 2) + p;
                m1 = fmaxf(m1, sm[O_H1 + off]);
                m2 = fmaxf(m2, sm[O_H2 + off]);
                m3 = fmaxf(m3, sm[O_H3 + off]);
                m4 = fmaxf(m4, sm[O_H4 + off]);
            }
            out[orow +       j] = m4;
            out[orow +  64 + j] = m3;
            out[orow + 128 + j] = m2;
            out[orow + 192 + j] = m1;
            out[orow + 256 + j] = x[(size_t)pt * 64 + j];
        }
        __syncthreads();
    }
}

extern "C" void kernel_launch(void* const* d_in, const int* in_sizes, int n_in,
                              void* d_out, int out_size) {
    const float* x   = (const float*)d_in[0];
    const float* pos = (const float*)d_in[1];
    const float* Wf  = (const float*)d_in[2];
    const float* bf  = (const float*)d_in[3];
    const float* Wm1 = (const float*)d_in[4];
    const float* bm1 = (const float*)d_in[5];
    const float* Wm2 = (const float*)d_in[6];
    const float* bm2 = (const float*)d_in[7];
    const float* Wl  = (const float*)d_in[8];
    const float* bl  = (const float*)d_in[9];
    float* out = (float*)d_out;

    cudaFuncSetAttribute(knn_kernel, cudaFuncAttributeMaxDynamicSharedMemorySize, 85248);
    cudaFuncSetAttribute(const_kernel, cudaFuncAttributeMaxDynamicSharedMemorySize,
                         (64 * 256 + 256 + 64) * 4);
    cudaFuncSetAttribute(edge_mlp_kernel, cudaFuncAttributeMaxDynamicSharedMemorySize,
                         SMEM_FLOATS * 4);

    knn_kernel<<<256, 256, 85248>>>(pos);
    const_kernel<<<256, 256, (64 * 256 + 256 + 64) * 4>>>(x, Wf, bf, Wm1, bm1, Wm2, bm2, Wl, bl);
    edge_mlp_kernel<<<148, 256, SMEM_FLOATS * 4>>>(x, Wf, Wm1, Wm2, Wl, out);
}